// round 2
// baseline (speedup 1.0000x reference)
#include <cuda_runtime.h>
#include <cstdint>
#include <cstddef>

// Problem dims
#define B_  512
#define S_  1024
#define I_  64
#define H_  128
#define G_  384   // 3*H
#define C_  10

// Scratch (device globals: allocation APIs are forbidden)
__device__ float g_xg[(size_t)B_ * S_ * G_];    // 805 MB: input-gate preactivations (reused by both layers)
__device__ float g_h1[(size_t)B_ * S_ * H_];    // 256 MB: layer0 hidden outputs
__device__ float g_h2last[B_ * H_];             // last hidden of layer1

typedef unsigned long long u64;

__device__ __forceinline__ u64 pk2(float lo, float hi) {
    u64 r; asm("mov.b64 %0, {%1, %2};" : "=l"(r) : "f"(lo), "f"(hi)); return r;
}
__device__ __forceinline__ void upk2(u64 v, float& lo, float& hi) {
    asm("mov.b64 {%0, %1}, %2;" : "=f"(lo), "=f"(hi) : "l"(v));
}
__device__ __forceinline__ void fma2(u64& d, u64 a, u64 b) {
    asm("fma.rn.f32x2 %0, %1, %2, %0;" : "+l"(d) : "l"(a), "l"(b));
}

__device__ __forceinline__ float sigf(float x) {
    float e = __expf(-x);
    return __fdividef(1.0f, 1.0f + e);
}
__device__ __forceinline__ float tanhf_fast(float x) {
    float ax = fabsf(x);
    float e = __expf(-2.0f * ax);
    float t = __fdividef(1.0f - e, 1.0f + e);
    return copysignf(t, x);
}

// ============================================================================
// Phase 1/3: xg[m][g] = sum_k A[m][k] * W[g][k] + bias[g]
// A: [M, K] row-major (M = B*S), W: [384, K], output -> g_xg [M, 384].
// Persistent CTAs; W held k-major in smem for the whole kernel; 64-row M tiles.
// fp32x2 FMA throughout (2x FFMA rate).
// Thread map: cg = lane (0..31) -> cols {4*cg + 128*gg + 0..3, gg=0..2},
//             rg = warp (0..7)  -> rows {8*rg .. 8*rg+7}.
// ============================================================================
template<int K, bool A_IS_H1>
__global__ __launch_bounds__(256) void gemm_xg_kernel(
    const float* __restrict__ Ain, const float* __restrict__ W,
    const float* __restrict__ bias, int ntiles)
{
    extern __shared__ float smem[];
    float* Ws = smem;              // [K][384], k-major
    float* As = smem + K * G_;     // [64][K], natural row-major
    const float* A = A_IS_H1 ? g_h1 : Ain;

    const int tid = threadIdx.x;

    // Transpose W into smem once: Ws[k][g] = W[g][k]
    for (int idx = tid; idx < G_ * (K / 4); idx += 256) {
        int kq = idx / G_;
        int g  = idx - kq * G_;
        float4 w4 = *reinterpret_cast<const float4*>(W + (size_t)g * K + 4 * kq);
        Ws[(4 * kq + 0) * G_ + g] = w4.x;
        Ws[(4 * kq + 1) * G_ + g] = w4.y;
        Ws[(4 * kq + 2) * G_ + g] = w4.z;
        Ws[(4 * kq + 3) * G_ + g] = w4.w;
    }

    const int cg = tid & 31;
    const int rg = tid >> 5;

    float4 bv[3];
#pragma unroll
    for (int gg = 0; gg < 3; ++gg)
        bv[gg] = *reinterpret_cast<const float4*>(bias + gg * H_ + 4 * cg);

    __syncthreads();

    for (int tile = blockIdx.x; tile < ntiles; tile += gridDim.x) {
        // Load A tile [64][K], fully coalesced float4
        const float4* Ab = reinterpret_cast<const float4*>(A + (size_t)tile * 64 * K);
        for (int idx = tid; idx < 64 * K / 4; idx += 256)
            reinterpret_cast<float4*>(As)[idx] = Ab[idx];
        __syncthreads();

        u64 acc[8][3][2];
#pragma unroll
        for (int r = 0; r < 8; ++r)
#pragma unroll
            for (int gg = 0; gg < 3; ++gg) {
                acc[r][gg][0] = 0ull;
                acc[r][gg][1] = 0ull;
            }

        for (int k4 = 0; k4 < K; k4 += 4) {
            float4 af[8];
#pragma unroll
            for (int r = 0; r < 8; ++r)   // broadcast LDS.128 (all lanes same addr)
                af[r] = *reinterpret_cast<const float4*>(&As[(rg * 8 + r) * K + k4]);
#pragma unroll
            for (int kk = 0; kk < 4; ++kk) {
                ulonglong2 wp[3];
#pragma unroll
                for (int gg = 0; gg < 3; ++gg)   // lane-contiguous LDS.128, pairs come free
                    wp[gg] = *reinterpret_cast<const ulonglong2*>(
                        &Ws[(size_t)(k4 + kk) * G_ + gg * H_ + 4 * cg]);
#pragma unroll
                for (int r = 0; r < 8; ++r) {
                    float a = (kk == 0) ? af[r].x : (kk == 1) ? af[r].y
                            : (kk == 2) ? af[r].z : af[r].w;
                    u64 ad = pk2(a, a);
#pragma unroll
                    for (int gg = 0; gg < 3; ++gg) {
                        fma2(acc[r][gg][0], ad, wp[gg].x);
                        fma2(acc[r][gg][1], ad, wp[gg].y);
                    }
                }
            }
        }

        float* Cb = g_xg + (size_t)tile * 64 * G_;
#pragma unroll
        for (int r = 0; r < 8; ++r) {
#pragma unroll
            for (int gg = 0; gg < 3; ++gg) {
                float x0, x1, x2, x3;
                upk2(acc[r][gg][0], x0, x1);
                upk2(acc[r][gg][1], x2, x3);
                float4 o = make_float4(x0 + bv[gg].x, x1 + bv[gg].y,
                                       x2 + bv[gg].z, x3 + bv[gg].w);
                *reinterpret_cast<float4*>(&Cb[(size_t)(rg * 8 + r) * G_ + gg * H_ + 4 * cg]) = o;
            }
        }
        __syncthreads();
    }
}

// ============================================================================
// Phase 2/4: recurrent scan. 128 CTAs x 4 batch rows, 384 threads.
// Thread g owns gate column g; its W_hh column (128 floats) lives in registers.
// h state [128 k][4 rows] in smem, broadcast-read via LDS.128 during the dot.
// Gates: g<128 -> r, 128..255 -> z, 256..383 -> n + h update.
// ============================================================================
template<bool WRITE_ALL>
__global__ __launch_bounds__(384, 1) void gru_rec_kernel(
    const float* __restrict__ Whh, const float* __restrict__ bhh)
{
    __shared__ float4 h_s[H_];
    __shared__ float4 rbuf[H_];
    __shared__ float4 zbuf[H_];

    const int g  = threadIdx.x;
    const int rb = blockIdx.x * 4;

    float w[H_];
#pragma unroll
    for (int k = 0; k < H_; ++k)
        w[k] = Whh[(size_t)g * H_ + k];
    const float bh = bhh[g];

    if (g < H_) h_s[g] = make_float4(0.f, 0.f, 0.f, 0.f);
    __syncthreads();

    const int sec = g >> 7;
    const int j   = g & 127;

    const size_t rstride = (size_t)S_ * G_;
    const float* xp = g_xg + (size_t)rb * rstride + g;   // advance by G_ per step
    float* hall = g_h1 + ((size_t)rb * S_) * H_ + j;     // advance by H_ per step

    for (int t = 0; t < S_; ++t) {
        // xg loads for the 4 rows: issued now, consumed ~1500 cyc later (after dot)
        float xv0 = __ldg(xp);
        float xv1 = __ldg(xp + rstride);
        float xv2 = __ldg(xp + 2 * rstride);
        float xv3 = __ldg(xp + 3 * rstride);
        xp += G_;

        u64 acc01 = 0ull, acc23 = 0ull;
#pragma unroll
        for (int k = 0; k < H_; ++k) {
            ulonglong2 hv = *reinterpret_cast<const ulonglong2*>(&h_s[k]);
            u64 wd = pk2(w[k], w[k]);
            fma2(acc01, hv.x, wd);
            fma2(acc23, hv.y, wd);
        }
        float g0, g1, g2, g3;
        upk2(acc01, g0, g1);
        upk2(acc23, g2, g3);
        g0 += bh; g1 += bh; g2 += bh; g3 += bh;

        if (sec == 0) {
            rbuf[j] = make_float4(sigf(xv0 + g0), sigf(xv1 + g1),
                                  sigf(xv2 + g2), sigf(xv3 + g3));
        } else if (sec == 1) {
            zbuf[j] = make_float4(sigf(xv0 + g0), sigf(xv1 + g1),
                                  sigf(xv2 + g2), sigf(xv3 + g3));
        }
        __syncthreads();
        if (sec == 2) {
            float4 rr = rbuf[j];
            float4 zz = zbuf[j];
            float4 ho = h_s[j];
            float n0 = tanhf_fast(xv0 + rr.x * g0);
            float n1 = tanhf_fast(xv1 + rr.y * g1);
            float n2 = tanhf_fast(xv2 + rr.z * g2);
            float n3 = tanhf_fast(xv3 + rr.w * g3);
            float h0 = n0 + zz.x * (ho.x - n0);
            float h1 = n1 + zz.y * (ho.y - n1);
            float h2 = n2 + zz.z * (ho.z - n2);
            float h3 = n3 + zz.w * (ho.w - n3);
            h_s[j] = make_float4(h0, h1, h2, h3);
            if (WRITE_ALL) {
                hall[0]                        = h0;
                hall[(size_t)S_ * H_]          = h1;
                hall[2 * (size_t)S_ * H_]      = h2;
                hall[3 * (size_t)S_ * H_]      = h3;
            } else if (t == S_ - 1) {
                g_h2last[(rb + 0) * H_ + j] = h0;
                g_h2last[(rb + 1) * H_ + j] = h1;
                g_h2last[(rb + 2) * H_ + j] = h2;
                g_h2last[(rb + 3) * H_ + j] = h3;
            }
        }
        __syncthreads();
        if (WRITE_ALL) hall += H_;
    }
}

// ============================================================================
// Phase 5: out[b][c] = h2last[b] . fc_w[c] + fc_b[c]
// ============================================================================
__global__ __launch_bounds__(128) void fc_kernel(
    const float* __restrict__ fw, const float* __restrict__ fb,
    float* __restrict__ out)
{
    __shared__ float sh[H_];
    const int b = blockIdx.x;
    sh[threadIdx.x] = g_h2last[b * H_ + threadIdx.x];
    __syncthreads();
    if (threadIdx.x < C_) {
        const int c = threadIdx.x;
        float acc = fb[c];
#pragma unroll
        for (int jj = 0; jj < H_; ++jj)
            acc += sh[jj] * fw[c * H_ + jj];
        out[b * C_ + c] = acc;
    }
}

extern "C" void kernel_launch(void* const* d_in, const int* in_sizes, int n_in,
                              void* d_out, int out_size)
{
    (void)in_sizes; (void)n_in; (void)out_size;
    const float* x      = (const float*)d_in[0];
    const float* W_ih0  = (const float*)d_in[1];
    const float* W_hh0  = (const float*)d_in[2];
    const float* b_ih0  = (const float*)d_in[3];
    const float* b_hh0  = (const float*)d_in[4];
    const float* W_ih1  = (const float*)d_in[5];
    const float* W_hh1  = (const float*)d_in[6];
    const float* b_ih1  = (const float*)d_in[7];
    const float* b_hh1  = (const float*)d_in[8];
    const float* fc_w   = (const float*)d_in[9];
    const float* fc_b   = (const float*)d_in[10];
    float* out = (float*)d_out;

    const int ntiles = (B_ * S_) / 64;   // 8192
    const int smem64  = 64  * 4 * (G_ + 64);   // 114688 B
    const int smem128 = 128 * 4 * (G_ + 64);   // 229376 B

    cudaFuncSetAttribute(gemm_xg_kernel<64, false>,
                         cudaFuncAttributeMaxDynamicSharedMemorySize, smem64);
    cudaFuncSetAttribute(gemm_xg_kernel<128, true>,
                         cudaFuncAttributeMaxDynamicSharedMemorySize, smem128);

    // Layer 0
    gemm_xg_kernel<64, false><<<148, 256, smem64>>>(x, W_ih0, b_ih0, ntiles);
    gru_rec_kernel<true><<<128, 384>>>(W_hh0, b_hh0);
    // Layer 1
    gemm_xg_kernel<128, true><<<148, 256, smem128>>>(nullptr, W_ih1, b_ih1, ntiles);
    gru_rec_kernel<false><<<128, 384>>>(W_hh1, b_hh1);
    // Head
    fc_kernel<<<B_, 128>>>(fc_w, fc_b, out);
}

// round 3
// speedup vs baseline: 1.0239x; 1.0239x over previous
#include <cuda_runtime.h>
#include <cstdint>
#include <cstddef>

// Problem dims
#define B_  512
#define S_  1024
#define I_  64
#define H_  128
#define G_  384   // 3*H
#define C_  10

// Scratch (device globals: allocation APIs are forbidden)
__device__ float g_xg[(size_t)B_ * S_ * G_];    // input-gate preactivations (reused by both layers)
__device__ float g_h1[(size_t)B_ * S_ * H_];    // layer0 hidden outputs
__device__ float g_h2last[B_ * H_];             // last hidden of layer1

typedef unsigned long long u64;

__device__ __forceinline__ u64 pk2(float lo, float hi) {
    u64 r; asm("mov.b64 %0, {%1, %2};" : "=l"(r) : "f"(lo), "f"(hi)); return r;
}
__device__ __forceinline__ void upk2(u64 v, float& lo, float& hi) {
    asm("mov.b64 {%0, %1}, %2;" : "=f"(lo), "=f"(hi) : "l"(v));
}
__device__ __forceinline__ void fma2(u64& d, u64 a, u64 b) {
    asm("fma.rn.f32x2 %0, %1, %2, %0;" : "+l"(d) : "l"(a), "l"(b));
}

__device__ __forceinline__ float sigf(float x) {
    float e = __expf(-x);
    return __fdividef(1.0f, 1.0f + e);
}
__device__ __forceinline__ float tanhf_fast(float x) {
    float ax = fabsf(x);
    float e = __expf(-2.0f * ax);
    float t = __fdividef(1.0f - e, 1.0f + e);
    return copysignf(t, x);
}

// ============================================================================
// Phase 1/3: xg[m][g] = sum_k A[m][k] * W[g][k] + bias[g]
// Persistent CTAs; W held k-major in smem; 64-row M tiles; fp32x2 FMA.
// ============================================================================
template<int K, bool A_IS_H1>
__global__ __launch_bounds__(256) void gemm_xg_kernel(
    const float* __restrict__ Ain, const float* __restrict__ W,
    const float* __restrict__ bias, int ntiles)
{
    extern __shared__ float smem[];
    float* Ws = smem;              // [K][384], k-major
    float* As = smem + K * G_;     // [64][K]
    const float* A = A_IS_H1 ? g_h1 : Ain;

    const int tid = threadIdx.x;

    for (int idx = tid; idx < G_ * (K / 4); idx += 256) {
        int kq = idx / G_;
        int g  = idx - kq * G_;
        float4 w4 = *reinterpret_cast<const float4*>(W + (size_t)g * K + 4 * kq);
        Ws[(4 * kq + 0) * G_ + g] = w4.x;
        Ws[(4 * kq + 1) * G_ + g] = w4.y;
        Ws[(4 * kq + 2) * G_ + g] = w4.z;
        Ws[(4 * kq + 3) * G_ + g] = w4.w;
    }

    const int cg = tid & 31;
    const int rg = tid >> 5;

    float4 bv[3];
#pragma unroll
    for (int gg = 0; gg < 3; ++gg)
        bv[gg] = *reinterpret_cast<const float4*>(bias + gg * H_ + 4 * cg);

    __syncthreads();

    for (int tile = blockIdx.x; tile < ntiles; tile += gridDim.x) {
        const float4* Ab = reinterpret_cast<const float4*>(A + (size_t)tile * 64 * K);
        for (int idx = tid; idx < 64 * K / 4; idx += 256)
            reinterpret_cast<float4*>(As)[idx] = Ab[idx];
        __syncthreads();

        u64 acc[8][3][2];
#pragma unroll
        for (int r = 0; r < 8; ++r)
#pragma unroll
            for (int gg = 0; gg < 3; ++gg) {
                acc[r][gg][0] = 0ull;
                acc[r][gg][1] = 0ull;
            }

        for (int k4 = 0; k4 < K; k4 += 4) {
            float4 af[8];
#pragma unroll
            for (int r = 0; r < 8; ++r)
                af[r] = *reinterpret_cast<const float4*>(&As[(rg * 8 + r) * K + k4]);
#pragma unroll
            for (int kk = 0; kk < 4; ++kk) {
                ulonglong2 wp[3];
#pragma unroll
                for (int gg = 0; gg < 3; ++gg)
                    wp[gg] = *reinterpret_cast<const ulonglong2*>(
                        &Ws[(size_t)(k4 + kk) * G_ + gg * H_ + 4 * cg]);
#pragma unroll
                for (int r = 0; r < 8; ++r) {
                    float a = (kk == 0) ? af[r].x : (kk == 1) ? af[r].y
                            : (kk == 2) ? af[r].z : af[r].w;
                    u64 ad = pk2(a, a);
#pragma unroll
                    for (int gg = 0; gg < 3; ++gg) {
                        fma2(acc[r][gg][0], ad, wp[gg].x);
                        fma2(acc[r][gg][1], ad, wp[gg].y);
                    }
                }
            }
        }

        float* Cb = g_xg + (size_t)tile * 64 * G_;
#pragma unroll
        for (int r = 0; r < 8; ++r) {
#pragma unroll
            for (int gg = 0; gg < 3; ++gg) {
                float x0, x1, x2, x3;
                upk2(acc[r][gg][0], x0, x1);
                upk2(acc[r][gg][1], x2, x3);
                float4 o = make_float4(x0 + bv[gg].x, x1 + bv[gg].y,
                                       x2 + bv[gg].z, x3 + bv[gg].w);
                *reinterpret_cast<float4*>(&Cb[(size_t)(rg * 8 + r) * G_ + gg * H_ + 4 * cg]) = o;
            }
        }
        __syncthreads();
    }
}

// ============================================================================
// Phase 2/4: recurrent scan. 128 CTAs x 4 batch rows, 384 threads.
// Thread g owns gate column g; W_hh column held as 64 pre-packed u64 pairs in
// registers. The fp32x2 pairing is along k: acc += (w[k],w[k+1])*(h[k],h[k+1]).
// h state laid out [4 rows][128 k] in smem; each LDS.128 (broadcast) feeds two
// fma2 per row, 4 independent acc chains.
// ============================================================================
template<bool WRITE_ALL>
__global__ __launch_bounds__(384, 1) void gru_rec_kernel(
    const float* __restrict__ Whh, const float* __restrict__ bhh)
{
    __shared__ float h_s[4][H_];
    __shared__ float4 rbuf[H_];
    __shared__ float4 zbuf[H_];

    const int g  = threadIdx.x;
    const int rb = blockIdx.x * 4;

    // W_hh row as 64 packed (w[2k], w[2k+1]) u64s — loop-invariant, in registers
    u64 wp[64];
    const u64* wrow = reinterpret_cast<const u64*>(Whh + (size_t)g * H_);
#pragma unroll
    for (int kk = 0; kk < 64; ++kk) wp[kk] = wrow[kk];
    const float bh = bhh[g];

    for (int idx = g; idx < 4 * H_; idx += 384)
        (&h_s[0][0])[idx] = 0.f;
    __syncthreads();

    const int sec = g >> 7;
    const int j   = g & 127;

    const size_t rstride = (size_t)S_ * G_;
    const float* xp = g_xg + (size_t)rb * rstride + g;
    float* hall = g_h1 + ((size_t)rb * S_) * H_ + j;

    const ulonglong2* hr0 = reinterpret_cast<const ulonglong2*>(h_s[0]);
    const ulonglong2* hr1 = reinterpret_cast<const ulonglong2*>(h_s[1]);
    const ulonglong2* hr2 = reinterpret_cast<const ulonglong2*>(h_s[2]);
    const ulonglong2* hr3 = reinterpret_cast<const ulonglong2*>(h_s[3]);

    for (int t = 0; t < S_; ++t) {
        // xg loads for the 4 rows: issued now, consumed after the dot
        float xv0 = __ldg(xp);
        float xv1 = __ldg(xp + rstride);
        float xv2 = __ldg(xp + 2 * rstride);
        float xv3 = __ldg(xp + 3 * rstride);
        xp += G_;

        u64 a0 = 0ull, a1 = 0ull, a2 = 0ull, a3 = 0ull;
#pragma unroll
        for (int kk = 0; kk < 32; ++kk) {
            ulonglong2 h0 = hr0[kk];
            ulonglong2 h1 = hr1[kk];
            ulonglong2 h2 = hr2[kk];
            ulonglong2 h3 = hr3[kk];
            u64 w0 = wp[2 * kk];
            u64 w1 = wp[2 * kk + 1];
            fma2(a0, h0.x, w0);
            fma2(a1, h1.x, w0);
            fma2(a2, h2.x, w0);
            fma2(a3, h3.x, w0);
            fma2(a0, h0.y, w1);
            fma2(a1, h1.y, w1);
            fma2(a2, h2.y, w1);
            fma2(a3, h3.y, w1);
        }
        float g0, g1, g2, g3, tlo, thi;
        upk2(a0, tlo, thi); g0 = tlo + thi + bh;
        upk2(a1, tlo, thi); g1 = tlo + thi + bh;
        upk2(a2, tlo, thi); g2 = tlo + thi + bh;
        upk2(a3, tlo, thi); g3 = tlo + thi + bh;

        if (sec == 0) {
            rbuf[j] = make_float4(sigf(xv0 + g0), sigf(xv1 + g1),
                                  sigf(xv2 + g2), sigf(xv3 + g3));
        } else if (sec == 1) {
            zbuf[j] = make_float4(sigf(xv0 + g0), sigf(xv1 + g1),
                                  sigf(xv2 + g2), sigf(xv3 + g3));
        }
        __syncthreads();
        if (sec == 2) {
            float4 rr = rbuf[j];
            float4 zz = zbuf[j];
            float ho0 = h_s[0][j], ho1 = h_s[1][j], ho2 = h_s[2][j], ho3 = h_s[3][j];
            float n0 = tanhf_fast(xv0 + rr.x * g0);
            float n1 = tanhf_fast(xv1 + rr.y * g1);
            float n2 = tanhf_fast(xv2 + rr.z * g2);
            float n3 = tanhf_fast(xv3 + rr.w * g3);
            float h0 = n0 + zz.x * (ho0 - n0);
            float h1 = n1 + zz.y * (ho1 - n1);
            float h2 = n2 + zz.z * (ho2 - n2);
            float h3 = n3 + zz.w * (ho3 - n3);
            h_s[0][j] = h0;
            h_s[1][j] = h1;
            h_s[2][j] = h2;
            h_s[3][j] = h3;
            if (WRITE_ALL) {
                hall[0]                        = h0;
                hall[(size_t)S_ * H_]          = h1;
                hall[2 * (size_t)S_ * H_]      = h2;
                hall[3 * (size_t)S_ * H_]      = h3;
            } else if (t == S_ - 1) {
                g_h2last[(rb + 0) * H_ + j] = h0;
                g_h2last[(rb + 1) * H_ + j] = h1;
                g_h2last[(rb + 2) * H_ + j] = h2;
                g_h2last[(rb + 3) * H_ + j] = h3;
            }
        }
        __syncthreads();
        if (WRITE_ALL) hall += H_;
    }
}

// ============================================================================
// Phase 5: out[b][c] = h2last[b] . fc_w[c] + fc_b[c]
// ============================================================================
__global__ __launch_bounds__(128) void fc_kernel(
    const float* __restrict__ fw, const float* __restrict__ fb,
    float* __restrict__ out)
{
    __shared__ float sh[H_];
    const int b = blockIdx.x;
    sh[threadIdx.x] = g_h2last[b * H_ + threadIdx.x];
    __syncthreads();
    if (threadIdx.x < C_) {
        const int c = threadIdx.x;
        float acc = fb[c];
#pragma unroll
        for (int jj = 0; jj < H_; ++jj)
            acc += sh[jj] * fw[c * H_ + jj];
        out[b * C_ + c] = acc;
    }
}

extern "C" void kernel_launch(void* const* d_in, const int* in_sizes, int n_in,
                              void* d_out, int out_size)
{
    (void)in_sizes; (void)n_in; (void)out_size;
    const float* x      = (const float*)d_in[0];
    const float* W_ih0  = (const float*)d_in[1];
    const float* W_hh0  = (const float*)d_in[2];
    const float* b_ih0  = (const float*)d_in[3];
    const float* b_hh0  = (const float*)d_in[4];
    const float* W_ih1  = (const float*)d_in[5];
    const float* W_hh1  = (const float*)d_in[6];
    const float* b_ih1  = (const float*)d_in[7];
    const float* b_hh1  = (const float*)d_in[8];
    const float* fc_w   = (const float*)d_in[9];
    const float* fc_b   = (const float*)d_in[10];
    float* out = (float*)d_out;

    const int ntiles = (B_ * S_) / 64;   // 8192
    const int smem64  = 64  * 4 * (G_ + 64);   // 114688 B
    const int smem128 = 128 * 4 * (G_ + 64);   // 229376 B

    cudaFuncSetAttribute(gemm_xg_kernel<64, false>,
                         cudaFuncAttributeMaxDynamicSharedMemorySize, smem64);
    cudaFuncSetAttribute(gemm_xg_kernel<128, true>,
                         cudaFuncAttributeMaxDynamicSharedMemorySize, smem128);

    // Layer 0
    gemm_xg_kernel<64, false><<<148, 256, smem64>>>(x, W_ih0, b_ih0, ntiles);
    gru_rec_kernel<true><<<128, 384>>>(W_hh0, b_hh0);
    // Layer 1
    gemm_xg_kernel<128, true><<<148, 256, smem128>>>(nullptr, W_ih1, b_ih1, ntiles);
    gru_rec_kernel<false><<<128, 384>>>(W_hh1, b_hh1);
    // Head
    fc_kernel<<<B_, 128>>>(fc_w, fc_b, out);
}